// round 9
// baseline (speedup 1.0000x reference)
#include <cuda_runtime.h>
#include <cuda_fp16.h>

// Problem constants (from metadata): x[512,1024,64], W*[128,192], b*[128],
// Wfc[10,128], bfc[10], out[512,10] fp32.
#define B_TOT    512
#define T_LEN    1024
#define I_DIM    64
#define H_DIM    128
#define C_DIM    10
#define KDIM     192      // I + H
#define NGATES   512      // 4*H, rows: [0,128)=f, [128,256)=o, [256,384)=i, [384,512)=g
#define ROWSTR   200      // padded row stride in halves (400 B -> conflict-free LDS.128)
#define BPC      4        // batch rows per CTA
#define NTHREADS 256
#define NCTAS    (B_TOT / BPC)   // 128

// SMEM layout (bytes)
#define SM_W_BYTES    (NGATES * ROWSTR * 2)          // 204800
#define SM_ACTS_OFF   SM_W_BYTES                     // BPC * KDIM floats = 3072
#define SM_OG_OFF     (SM_ACTS_OFF + BPC * KDIM * 4) // 2 * BPC * 128 floats = 4096
#define SM_TOTAL      (SM_OG_OFF + 2 * BPC * H_DIM * 4)   // 211968

// Packed dual-fp32 FMA (Blackwell f32x2 pipe): d = a*b + c elementwise on pairs.
__device__ __forceinline__ float2 ffma2(float2 a, float2 b, float2 c) {
    float2 d;
    asm("{\n\t"
        ".reg .b64 ra, rb, rc, rd;\n\t"
        "mov.b64 ra, {%2, %3};\n\t"
        "mov.b64 rb, {%4, %5};\n\t"
        "mov.b64 rc, {%6, %7};\n\t"
        "fma.rn.f32x2 rd, ra, rb, rc;\n\t"
        "mov.b64 {%0, %1}, rd;\n\t"
        "}"
        : "=f"(d.x), "=f"(d.y)
        : "f"(a.x), "f"(a.y), "f"(b.x), "f"(b.y), "f"(c.x), "f"(c.y));
    return d;
}

__device__ __forceinline__ float sigmoidf_fast(float z) {
    return 1.0f / (1.0f + __expf(-z));
}
__device__ __forceinline__ float tanhf_fast(float z) {
    // tanh(z) = 2*sigmoid(2z) - 1; saturates correctly for |z| large.
    return 2.0f / (1.0f + __expf(-2.0f * z)) - 1.0f;
}

__global__ void __launch_bounds__(NTHREADS, 1)
lstm_persistent_kernel(const float* __restrict__ x,
                       const float* __restrict__ Wf, const float* __restrict__ bf,
                       const float* __restrict__ Wo, const float* __restrict__ bo,
                       const float* __restrict__ Wi, const float* __restrict__ bi,
                       const float* __restrict__ Wg, const float* __restrict__ bg,
                       const float* __restrict__ Wfc, const float* __restrict__ bfc,
                       float* __restrict__ out)
{
    extern __shared__ char smem[];
    __half* Wsm  = reinterpret_cast<__half*>(smem);
    float*  acts = reinterpret_cast<float*>(smem + SM_ACTS_OFF); // [BPC][KDIM]
    float*  og   = reinterpret_cast<float*>(smem + SM_OG_OFF);   // [2][BPC][128]

    const int tid = threadIdx.x;
    const int b0  = blockIdx.x * BPC;

    // ---- One-time: convert weights fp32 -> fp16 into SMEM ----
    {
        const float* Wsrc0 = Wf; const float* Wsrc1 = Wo;
        const float* Wsrc2 = Wi; const float* Wsrc3 = Wg;
        for (int idx = tid; idx < NGATES * KDIM; idx += NTHREADS) {
            int row = idx / KDIM;
            int col = idx - row * KDIM;
            int g   = row >> 7;          // 0..3
            int lr  = row & 127;
            const float* src = (g == 0) ? Wsrc0 : (g == 1) ? Wsrc1 : (g == 2) ? Wsrc2 : Wsrc3;
            Wsm[row * ROWSTR + col] = __float2half_rn(src[lr * KDIM + col]);
        }
    }

    // ---- Init activations: x(t=0) and h=0 ----
    for (int idx = tid; idx < BPC * H_DIM; idx += NTHREADS) {
        int b = idx >> 7, j = idx & 127;
        acts[b * KDIM + I_DIM + j] = 0.0f;
    }
    for (int idx = tid; idx < BPC * I_DIM; idx += NTHREADS) {
        int b = idx >> 6, i = idx & 63;
        acts[b * KDIM + i] = x[((size_t)(b0 + b) * T_LEN + 0) * I_DIM + i];
    }

    // ---- Per-thread gate-row assignment ----
    // thread j<128: rows (j, j+256)      = (f_j, i_j)
    // thread j>=128: rows (j, j+256)     = (o_{j-128}, g_{j-128})
    float bias0, bias1;
    if (tid < 128) { bias0 = bf[tid];       bias1 = bi[tid]; }
    else           { bias0 = bo[tid - 128]; bias1 = bg[tid - 128]; }

    const uint4* w0p = reinterpret_cast<const uint4*>(Wsm + (size_t)tid         * ROWSTR);
    const uint4* w1p = reinterpret_cast<const uint4*>(Wsm + (size_t)(tid + 256) * ROWSTR);

    float c_state[BPC];
#pragma unroll
    for (int b = 0; b < BPC; ++b) c_state[b] = 0.0f;

    // Each thread owns one x element slot for prefetch: batch bx, feature ix.
    const int bx = tid >> 6;
    const int ix = tid & 63;
    const float* xsrc = x + (size_t)(b0 + bx) * T_LEN * I_DIM + ix;

    __syncthreads();

    for (int t = 0; t < T_LEN; ++t) {
        // Prefetch x_{t+1}; consumed ~3000 cycles later.
        float xnext = 0.0f;
        if (t + 1 < T_LEN) xnext = __ldg(xsrc + (size_t)(t + 1) * I_DIM);

        float2 acc0[BPC], acc1[BPC];
#pragma unroll
        for (int b = 0; b < BPC; ++b) {
            acc0[b] = make_float2(0.0f, 0.0f);
            acc1[b] = make_float2(0.0f, 0.0f);
        }

#pragma unroll 4
        for (int kc = 0; kc < KDIM / 8; ++kc) {
            uint4 u0 = w0p[kc];   // 8 fp16 weights of row r0
            uint4 u1 = w1p[kc];   // 8 fp16 weights of row r1
            float2 w0a = __half22float2(*reinterpret_cast<const __half2*>(&u0.x));
            float2 w0b = __half22float2(*reinterpret_cast<const __half2*>(&u0.y));
            float2 w0c = __half22float2(*reinterpret_cast<const __half2*>(&u0.z));
            float2 w0d = __half22float2(*reinterpret_cast<const __half2*>(&u0.w));
            float2 w1a = __half22float2(*reinterpret_cast<const __half2*>(&u1.x));
            float2 w1b = __half22float2(*reinterpret_cast<const __half2*>(&u1.y));
            float2 w1c = __half22float2(*reinterpret_cast<const __half2*>(&u1.z));
            float2 w1d = __half22float2(*reinterpret_cast<const __half2*>(&u1.w));
#pragma unroll
            for (int b = 0; b < BPC; ++b) {
                const float4* ap = reinterpret_cast<const float4*>(acts + b * KDIM + kc * 8);
                float4 a0 = ap[0];
                float4 a1 = ap[1];
                float2 p0 = make_float2(a0.x, a0.y);
                float2 p1 = make_float2(a0.z, a0.w);
                float2 p2 = make_float2(a1.x, a1.y);
                float2 p3 = make_float2(a1.z, a1.w);
                acc0[b] = ffma2(w0a, p0, acc0[b]);
                acc0[b] = ffma2(w0b, p1, acc0[b]);
                acc0[b] = ffma2(w0c, p2, acc0[b]);
                acc0[b] = ffma2(w0d, p3, acc0[b]);
                acc1[b] = ffma2(w1a, p0, acc1[b]);
                acc1[b] = ffma2(w1b, p1, acc1[b]);
                acc1[b] = ffma2(w1c, p2, acc1[b]);
                acc1[b] = ffma2(w1d, p3, acc1[b]);
            }
        }

        __syncthreads();   // all reads of acts (x_t, h_t) complete

        if (tid >= 128) {
            const int jj = tid - 128;
#pragma unroll
            for (int b = 0; b < BPC; ++b) {
                float go = acc0[b].x + acc0[b].y + bias0;   // o preact
                float gg = acc1[b].x + acc1[b].y + bias1;   // g preact
                og[b * H_DIM + jj]                  = sigmoidf_fast(go);
                og[BPC * H_DIM + b * H_DIM + jj]    = tanhf_fast(gg);
            }
        }
        if (t + 1 < T_LEN) acts[bx * KDIM + ix] = xnext;  // stage x_{t+1}

        __syncthreads();   // og + x visible

        if (tid < 128) {
#pragma unroll
            for (int b = 0; b < BPC; ++b) {
                float gf = acc0[b].x + acc0[b].y + bias0;   // f preact
                float gi = acc1[b].x + acc1[b].y + bias1;   // i preact
                float fs = sigmoidf_fast(gf);
                float is = sigmoidf_fast(gi);
                float os = og[b * H_DIM + tid];
                float gt = og[BPC * H_DIM + b * H_DIM + tid];
                float c  = c_state[b] * fs + gt * is;
                c_state[b] = c;
                acts[b * KDIM + I_DIM + tid] = c * os;      // h_{t+1} (note: no tanh, per reference)
            }
        }

        __syncthreads();   // h visible for next step's GEMM
    }

    // ---- Final FC: out[b, c] = h[b,:] . Wfc[c,:] + bfc[c] ----
    for (int idx = tid; idx < BPC * C_DIM; idx += NTHREADS) {
        int b  = idx / C_DIM;
        int cc = idx - b * C_DIM;
        float s = bfc[cc];
        const float* hrow = acts + b * KDIM + I_DIM;
        const float* wrow = Wfc + cc * H_DIM;
#pragma unroll 8
        for (int k = 0; k < H_DIM; ++k)
            s += hrow[k] * wrow[k];
        out[(b0 + b) * C_DIM + cc] = s;
    }
}

extern "C" void kernel_launch(void* const* d_in, const int* in_sizes, int n_in,
                              void* d_out, int out_size)
{
    const float* x   = (const float*)d_in[0];
    const float* Wf  = (const float*)d_in[1];
    const float* bf  = (const float*)d_in[2];
    const float* Wo  = (const float*)d_in[3];
    const float* bo  = (const float*)d_in[4];
    const float* Wi  = (const float*)d_in[5];
    const float* bi  = (const float*)d_in[6];
    const float* Wg  = (const float*)d_in[7];
    const float* bg  = (const float*)d_in[8];
    const float* Wfc = (const float*)d_in[9];
    const float* bfc = (const float*)d_in[10];
    float* out = (float*)d_out;

    static bool attr_set = false;
    if (!attr_set) {
        cudaFuncSetAttribute(lstm_persistent_kernel,
                             cudaFuncAttributeMaxDynamicSharedMemorySize, SM_TOTAL);
        attr_set = true;
    }

    lstm_persistent_kernel<<<NCTAS, NTHREADS, SM_TOTAL>>>(
        x, Wf, bf, Wo, bo, Wi, bi, Wg, bg, Wfc, bfc, out);
}

// round 10
// speedup vs baseline: 1.0015x; 1.0015x over previous
#include <cuda_runtime.h>
#include <cuda_fp16.h>

// Problem constants (from metadata): x[512,1024,64], W*[128,192], b*[128],
// Wfc[10,128], bfc[10], out[512,10] fp32.
#define B_TOT    512
#define T_LEN    1024
#define I_DIM    64
#define H_DIM    128
#define C_DIM    10
#define KDIM     192      // I + H
#define NGATES   512      // 4*H, rows: [0,128)=f, [128,256)=o, [256,384)=i, [384,512)=g
#define ROWSTR   200      // padded row stride in halves (400 B -> conflict-free LDS.128)
#define BPC      4        // batch rows per CTA
#define NTHREADS 256
#define NCTAS    (B_TOT / BPC)   // 128

// SMEM layout (bytes)
#define SM_W_BYTES    (NGATES * ROWSTR * 2)          // 204800
#define SM_ACTS_OFF   SM_W_BYTES                     // BPC * KDIM floats = 3072
#define SM_OG_OFF     (SM_ACTS_OFF + BPC * KDIM * 4) // 2 * BPC * 128 floats = 4096
#define SM_TOTAL      (SM_OG_OFF + 2 * BPC * H_DIM * 4)   // 211968

// Packed dual-fp32 FMA (Blackwell f32x2 pipe): d = a*b + c elementwise on pairs.
__device__ __forceinline__ float2 ffma2(float2 a, float2 b, float2 c) {
    float2 d;
    asm("{\n\t"
        ".reg .b64 ra, rb, rc, rd;\n\t"
        "mov.b64 ra, {%2, %3};\n\t"
        "mov.b64 rb, {%4, %5};\n\t"
        "mov.b64 rc, {%6, %7};\n\t"
        "fma.rn.f32x2 rd, ra, rb, rc;\n\t"
        "mov.b64 {%0, %1}, rd;\n\t"
        "}"
        : "=f"(d.x), "=f"(d.y)
        : "f"(a.x), "f"(a.y), "f"(b.x), "f"(b.y), "f"(c.x), "f"(c.y));
    return d;
}

__device__ __forceinline__ float sigmoidf_fast(float z) {
    return 1.0f / (1.0f + __expf(-z));
}
__device__ __forceinline__ float tanhf_fast(float z) {
    // tanh(z) = 2*sigmoid(2z) - 1; saturates correctly for |z| large.
    return 2.0f / (1.0f + __expf(-2.0f * z)) - 1.0f;
}

__global__ void __launch_bounds__(NTHREADS, 1)
lstm_persistent_kernel(const float* __restrict__ x,
                       const float* __restrict__ Wf, const float* __restrict__ bf,
                       const float* __restrict__ Wo, const float* __restrict__ bo,
                       const float* __restrict__ Wi, const float* __restrict__ bi,
                       const float* __restrict__ Wg, const float* __restrict__ bg,
                       const float* __restrict__ Wfc, const float* __restrict__ bfc,
                       float* __restrict__ out)
{
    extern __shared__ char smem[];
    __half* Wsm  = reinterpret_cast<__half*>(smem);
    float*  acts = reinterpret_cast<float*>(smem + SM_ACTS_OFF); // [BPC][KDIM]
    float*  og   = reinterpret_cast<float*>(smem + SM_OG_OFF);   // [2][BPC][128]

    const int tid = threadIdx.x;
    const int b0  = blockIdx.x * BPC;

    // ---- One-time: convert weights fp32 -> fp16 into SMEM ----
    {
        const float* Wsrc0 = Wf; const float* Wsrc1 = Wo;
        const float* Wsrc2 = Wi; const float* Wsrc3 = Wg;
        for (int idx = tid; idx < NGATES * KDIM; idx += NTHREADS) {
            int row = idx / KDIM;
            int col = idx - row * KDIM;
            int g   = row >> 7;          // 0..3
            int lr  = row & 127;
            const float* src = (g == 0) ? Wsrc0 : (g == 1) ? Wsrc1 : (g == 2) ? Wsrc2 : Wsrc3;
            Wsm[row * ROWSTR + col] = __float2half_rn(src[lr * KDIM + col]);
        }
    }

    // ---- Init activations: x(t=0) and h=0 ----
    for (int idx = tid; idx < BPC * H_DIM; idx += NTHREADS) {
        int b = idx >> 7, j = idx & 127;
        acts[b * KDIM + I_DIM + j] = 0.0f;
    }
    for (int idx = tid; idx < BPC * I_DIM; idx += NTHREADS) {
        int b = idx >> 6, i = idx & 63;
        acts[b * KDIM + i] = x[((size_t)(b0 + b) * T_LEN + 0) * I_DIM + i];
    }

    // ---- Per-thread gate-row assignment ----
    // thread j<128: rows (j, j+256)      = (f_j, i_j)
    // thread j>=128: rows (j, j+256)     = (o_{j-128}, g_{j-128})
    float bias0, bias1;
    if (tid < 128) { bias0 = bf[tid];       bias1 = bi[tid]; }
    else           { bias0 = bo[tid - 128]; bias1 = bg[tid - 128]; }

    const uint4* w0p = reinterpret_cast<const uint4*>(Wsm + (size_t)tid         * ROWSTR);
    const uint4* w1p = reinterpret_cast<const uint4*>(Wsm + (size_t)(tid + 256) * ROWSTR);

    float c_state[BPC];
#pragma unroll
    for (int b = 0; b < BPC; ++b) c_state[b] = 0.0f;

    // Each thread owns one x element slot for prefetch: batch bx, feature ix.
    const int bx = tid >> 6;
    const int ix = tid & 63;
    const float* xsrc = x + (size_t)(b0 + bx) * T_LEN * I_DIM + ix;

    __syncthreads();

    for (int t = 0; t < T_LEN; ++t) {
        // Prefetch x_{t+1}; consumed ~3000 cycles later.
        float xnext = 0.0f;
        if (t + 1 < T_LEN) xnext = __ldg(xsrc + (size_t)(t + 1) * I_DIM);

        float2 acc0[BPC], acc1[BPC];
#pragma unroll
        for (int b = 0; b < BPC; ++b) {
            acc0[b] = make_float2(0.0f, 0.0f);
            acc1[b] = make_float2(0.0f, 0.0f);
        }

#pragma unroll 4
        for (int kc = 0; kc < KDIM / 8; ++kc) {
            uint4 u0 = w0p[kc];   // 8 fp16 weights of row r0
            uint4 u1 = w1p[kc];   // 8 fp16 weights of row r1
            float2 w0a = __half22float2(*reinterpret_cast<const __half2*>(&u0.x));
            float2 w0b = __half22float2(*reinterpret_cast<const __half2*>(&u0.y));
            float2 w0c = __half22float2(*reinterpret_cast<const __half2*>(&u0.z));
            float2 w0d = __half22float2(*reinterpret_cast<const __half2*>(&u0.w));
            float2 w1a = __half22float2(*reinterpret_cast<const __half2*>(&u1.x));
            float2 w1b = __half22float2(*reinterpret_cast<const __half2*>(&u1.y));
            float2 w1c = __half22float2(*reinterpret_cast<const __half2*>(&u1.z));
            float2 w1d = __half22float2(*reinterpret_cast<const __half2*>(&u1.w));
#pragma unroll
            for (int b = 0; b < BPC; ++b) {
                const float4* ap = reinterpret_cast<const float4*>(acts + b * KDIM + kc * 8);
                float4 a0 = ap[0];
                float4 a1 = ap[1];
                float2 p0 = make_float2(a0.x, a0.y);
                float2 p1 = make_float2(a0.z, a0.w);
                float2 p2 = make_float2(a1.x, a1.y);
                float2 p3 = make_float2(a1.z, a1.w);
                acc0[b] = ffma2(w0a, p0, acc0[b]);
                acc0[b] = ffma2(w0b, p1, acc0[b]);
                acc0[b] = ffma2(w0c, p2, acc0[b]);
                acc0[b] = ffma2(w0d, p3, acc0[b]);
                acc1[b] = ffma2(w1a, p0, acc1[b]);
                acc1[b] = ffma2(w1b, p1, acc1[b]);
                acc1[b] = ffma2(w1c, p2, acc1[b]);
                acc1[b] = ffma2(w1d, p3, acc1[b]);
            }
        }

        __syncthreads();   // all reads of acts (x_t, h_t) complete

        if (tid >= 128) {
            const int jj = tid - 128;
#pragma unroll
            for (int b = 0; b < BPC; ++b) {
                float go = acc0[b].x + acc0[b].y + bias0;   // o preact
                float gg = acc1[b].x + acc1[b].y + bias1;   // g preact
                og[b * H_DIM + jj]                  = sigmoidf_fast(go);
                og[BPC * H_DIM + b * H_DIM + jj]    = tanhf_fast(gg);
            }
        }
        if (t + 1 < T_LEN) acts[bx * KDIM + ix] = xnext;  // stage x_{t+1}

        __syncthreads();   // og + x visible

        if (tid < 128) {
#pragma unroll
            for (int b = 0; b < BPC; ++b) {
                float gf = acc0[b].x + acc0[b].y + bias0;   // f preact
                float gi = acc1[b].x + acc1[b].y + bias1;   // i preact
                float fs = sigmoidf_fast(gf);
                float is = sigmoidf_fast(gi);
                float os = og[b * H_DIM + tid];
                float gt = og[BPC * H_DIM + b * H_DIM + tid];
                float c  = c_state[b] * fs + gt * is;
                c_state[b] = c;
                acts[b * KDIM + I_DIM + tid] = c * os;      // h_{t+1} (note: no tanh, per reference)
            }
        }

        __syncthreads();   // h visible for next step's GEMM
    }

    // ---- Final FC: out[b, c] = h[b,:] . Wfc[c,:] + bfc[c] ----
    for (int idx = tid; idx < BPC * C_DIM; idx += NTHREADS) {
        int b  = idx / C_DIM;
        int cc = idx - b * C_DIM;
        float s = bfc[cc];
        const float* hrow = acts + b * KDIM + I_DIM;
        const float* wrow = Wfc + cc * H_DIM;
#pragma unroll 8
        for (int k = 0; k < H_DIM; ++k)
            s += hrow[k] * wrow[k];
        out[(b0 + b) * C_DIM + cc] = s;
    }
}

extern "C" void kernel_launch(void* const* d_in, const int* in_sizes, int n_in,
                              void* d_out, int out_size)
{
    const float* x   = (const float*)d_in[0];
    const float* Wf  = (const float*)d_in[1];
    const float* bf  = (const float*)d_in[2];
    const float* Wo  = (const float*)d_in[3];
    const float* bo  = (const float*)d_in[4];
    const float* Wi  = (const float*)d_in[5];
    const float* bi  = (const float*)d_in[6];
    const float* Wg  = (const float*)d_in[7];
    const float* bg  = (const float*)d_in[8];
    const float* Wfc = (const float*)d_in[9];
    const float* bfc = (const float*)d_in[10];
    float* out = (float*)d_out;

    static bool attr_set = false;
    if (!attr_set) {
        cudaFuncSetAttribute(lstm_persistent_kernel,
                             cudaFuncAttributeMaxDynamicSharedMemorySize, SM_TOTAL);
        attr_set = true;
    }

    lstm_persistent_kernel<<<NCTAS, NTHREADS, SM_TOTAL>>>(
        x, Wf, bf, Wo, bo, Wi, bi, Wg, bg, Wfc, bfc, out);
}

// round 11
// speedup vs baseline: 1.0025x; 1.0010x over previous
#include <cuda_runtime.h>
#include <cuda_fp16.h>

// Problem constants (from metadata): x[512,1024,64], W*[128,192], b*[128],
// Wfc[10,128], bfc[10], out[512,10] fp32.
#define B_TOT    512
#define T_LEN    1024
#define I_DIM    64
#define H_DIM    128
#define C_DIM    10
#define KDIM     192      // I + H
#define NGATES   512      // 4*H, rows: [0,128)=f, [128,256)=o, [256,384)=i, [384,512)=g
#define ROWSTR   200      // padded row stride in halves (400 B -> conflict-free LDS.128)
#define BPC      4        // batch rows per CTA
#define NTHREADS 256
#define NCTAS    (B_TOT / BPC)   // 128

// SMEM layout (bytes)
#define SM_W_BYTES    (NGATES * ROWSTR * 2)          // 204800
#define SM_ACTS_OFF   SM_W_BYTES                     // BPC * KDIM floats = 3072
#define SM_OG_OFF     (SM_ACTS_OFF + BPC * KDIM * 4) // 2 * BPC * 128 floats = 4096
#define SM_TOTAL      (SM_OG_OFF + 2 * BPC * H_DIM * 4)   // 211968

// Packed dual-fp32 FMA (Blackwell f32x2 pipe): d = a*b + c elementwise on pairs.
__device__ __forceinline__ float2 ffma2(float2 a, float2 b, float2 c) {
    float2 d;
    asm("{\n\t"
        ".reg .b64 ra, rb, rc, rd;\n\t"
        "mov.b64 ra, {%2, %3};\n\t"
        "mov.b64 rb, {%4, %5};\n\t"
        "mov.b64 rc, {%6, %7};\n\t"
        "fma.rn.f32x2 rd, ra, rb, rc;\n\t"
        "mov.b64 {%0, %1}, rd;\n\t"
        "}"
        : "=f"(d.x), "=f"(d.y)
        : "f"(a.x), "f"(a.y), "f"(b.x), "f"(b.y), "f"(c.x), "f"(c.y));
    return d;
}

__device__ __forceinline__ float sigmoidf_fast(float z) {
    return 1.0f / (1.0f + __expf(-z));
}
__device__ __forceinline__ float tanhf_fast(float z) {
    // tanh(z) = 2*sigmoid(2z) - 1; saturates correctly for |z| large.
    return 2.0f / (1.0f + __expf(-2.0f * z)) - 1.0f;
}

__global__ void __launch_bounds__(NTHREADS, 1)
lstm_persistent_kernel(const float* __restrict__ x,
                       const float* __restrict__ Wf, const float* __restrict__ bf,
                       const float* __restrict__ Wo, const float* __restrict__ bo,
                       const float* __restrict__ Wi, const float* __restrict__ bi,
                       const float* __restrict__ Wg, const float* __restrict__ bg,
                       const float* __restrict__ Wfc, const float* __restrict__ bfc,
                       float* __restrict__ out)
{
    extern __shared__ char smem[];
    __half* Wsm  = reinterpret_cast<__half*>(smem);
    float*  acts = reinterpret_cast<float*>(smem + SM_ACTS_OFF); // [BPC][KDIM]
    float*  og   = reinterpret_cast<float*>(smem + SM_OG_OFF);   // [2][BPC][128]

    const int tid = threadIdx.x;
    const int b0  = blockIdx.x * BPC;

    // ---- One-time: convert weights fp32 -> fp16 into SMEM ----
    {
        const float* Wsrc0 = Wf; const float* Wsrc1 = Wo;
        const float* Wsrc2 = Wi; const float* Wsrc3 = Wg;
        for (int idx = tid; idx < NGATES * KDIM; idx += NTHREADS) {
            int row = idx / KDIM;
            int col = idx - row * KDIM;
            int g   = row >> 7;          // 0..3
            int lr  = row & 127;
            const float* src = (g == 0) ? Wsrc0 : (g == 1) ? Wsrc1 : (g == 2) ? Wsrc2 : Wsrc3;
            Wsm[row * ROWSTR + col] = __float2half_rn(src[lr * KDIM + col]);
        }
    }

    // ---- Init activations: x(t=0) and h=0 ----
    for (int idx = tid; idx < BPC * H_DIM; idx += NTHREADS) {
        int b = idx >> 7, j = idx & 127;
        acts[b * KDIM + I_DIM + j] = 0.0f;
    }
    for (int idx = tid; idx < BPC * I_DIM; idx += NTHREADS) {
        int b = idx >> 6, i = idx & 63;
        acts[b * KDIM + i] = x[((size_t)(b0 + b) * T_LEN + 0) * I_DIM + i];
    }

    // ---- Per-thread gate-row assignment ----
    // thread j<128: rows (j, j+256)      = (f_j, i_j)
    // thread j>=128: rows (j, j+256)     = (o_{j-128}, g_{j-128})
    float bias0, bias1;
    if (tid < 128) { bias0 = bf[tid];       bias1 = bi[tid]; }
    else           { bias0 = bo[tid - 128]; bias1 = bg[tid - 128]; }

    const uint4* w0p = reinterpret_cast<const uint4*>(Wsm + (size_t)tid         * ROWSTR);
    const uint4* w1p = reinterpret_cast<const uint4*>(Wsm + (size_t)(tid + 256) * ROWSTR);

    float c_state[BPC];
#pragma unroll
    for (int b = 0; b < BPC; ++b) c_state[b] = 0.0f;

    // Each thread owns one x element slot for prefetch: batch bx, feature ix.
    const int bx = tid >> 6;
    const int ix = tid & 63;
    const float* xsrc = x + (size_t)(b0 + bx) * T_LEN * I_DIM + ix;

    __syncthreads();

    for (int t = 0; t < T_LEN; ++t) {
        // Prefetch x_{t+1}; consumed ~3000 cycles later.
        float xnext = 0.0f;
        if (t + 1 < T_LEN) xnext = __ldg(xsrc + (size_t)(t + 1) * I_DIM);

        float2 acc0[BPC], acc1[BPC];
#pragma unroll
        for (int b = 0; b < BPC; ++b) {
            acc0[b] = make_float2(0.0f, 0.0f);
            acc1[b] = make_float2(0.0f, 0.0f);
        }

#pragma unroll 4
        for (int kc = 0; kc < KDIM / 8; ++kc) {
            uint4 u0 = w0p[kc];   // 8 fp16 weights of row r0
            uint4 u1 = w1p[kc];   // 8 fp16 weights of row r1
            float2 w0a = __half22float2(*reinterpret_cast<const __half2*>(&u0.x));
            float2 w0b = __half22float2(*reinterpret_cast<const __half2*>(&u0.y));
            float2 w0c = __half22float2(*reinterpret_cast<const __half2*>(&u0.z));
            float2 w0d = __half22float2(*reinterpret_cast<const __half2*>(&u0.w));
            float2 w1a = __half22float2(*reinterpret_cast<const __half2*>(&u1.x));
            float2 w1b = __half22float2(*reinterpret_cast<const __half2*>(&u1.y));
            float2 w1c = __half22float2(*reinterpret_cast<const __half2*>(&u1.z));
            float2 w1d = __half22float2(*reinterpret_cast<const __half2*>(&u1.w));
#pragma unroll
            for (int b = 0; b < BPC; ++b) {
                const float4* ap = reinterpret_cast<const float4*>(acts + b * KDIM + kc * 8);
                float4 a0 = ap[0];
                float4 a1 = ap[1];
                float2 p0 = make_float2(a0.x, a0.y);
                float2 p1 = make_float2(a0.z, a0.w);
                float2 p2 = make_float2(a1.x, a1.y);
                float2 p3 = make_float2(a1.z, a1.w);
                acc0[b] = ffma2(w0a, p0, acc0[b]);
                acc0[b] = ffma2(w0b, p1, acc0[b]);
                acc0[b] = ffma2(w0c, p2, acc0[b]);
                acc0[b] = ffma2(w0d, p3, acc0[b]);
                acc1[b] = ffma2(w1a, p0, acc1[b]);
                acc1[b] = ffma2(w1b, p1, acc1[b]);
                acc1[b] = ffma2(w1c, p2, acc1[b]);
                acc1[b] = ffma2(w1d, p3, acc1[b]);
            }
        }

        __syncthreads();   // all reads of acts (x_t, h_t) complete

        if (tid >= 128) {
            const int jj = tid - 128;
#pragma unroll
            for (int b = 0; b < BPC; ++b) {
                float go = acc0[b].x + acc0[b].y + bias0;   // o preact
                float gg = acc1[b].x + acc1[b].y + bias1;   // g preact
                og[b * H_DIM + jj]                  = sigmoidf_fast(go);
                og[BPC * H_DIM + b * H_DIM + jj]    = tanhf_fast(gg);
            }
        }
        if (t + 1 < T_LEN) acts[bx * KDIM + ix] = xnext;  // stage x_{t+1}

        __syncthreads();   // og + x visible

        if (tid < 128) {
#pragma unroll
            for (int b = 0; b < BPC; ++b) {
                float gf = acc0[b].x + acc0[b].y + bias0;   // f preact
                float gi = acc1[b].x + acc1[b].y + bias1;   // i preact
                float fs = sigmoidf_fast(gf);
                float is = sigmoidf_fast(gi);
                float os = og[b * H_DIM + tid];
                float gt = og[BPC * H_DIM + b * H_DIM + tid];
                float c  = c_state[b] * fs + gt * is;
                c_state[b] = c;
                acts[b * KDIM + I_DIM + tid] = c * os;      // h_{t+1} (note: no tanh, per reference)
            }
        }

        __syncthreads();   // h visible for next step's GEMM
    }

    // ---- Final FC: out[b, c] = h[b,:] . Wfc[c,:] + bfc[c] ----
    for (int idx = tid; idx < BPC * C_DIM; idx += NTHREADS) {
        int b  = idx / C_DIM;
        int cc = idx - b * C_DIM;
        float s = bfc[cc];
        const float* hrow = acts + b * KDIM + I_DIM;
        const float* wrow = Wfc + cc * H_DIM;
#pragma unroll 8
        for (int k = 0; k < H_DIM; ++k)
            s += hrow[k] * wrow[k];
        out[(b0 + b) * C_DIM + cc] = s;
    }
}

extern "C" void kernel_launch(void* const* d_in, const int* in_sizes, int n_in,
                              void* d_out, int out_size)
{
    const float* x   = (const float*)d_in[0];
    const float* Wf  = (const float*)d_in[1];
    const float* bf  = (const float*)d_in[2];
    const float* Wo  = (const float*)d_in[3];
    const float* bo  = (const float*)d_in[4];
    const float* Wi  = (const float*)d_in[5];
    const float* bi  = (const float*)d_in[6];
    const float* Wg  = (const float*)d_in[7];
    const float* bg  = (const float*)d_in[8];
    const float* Wfc = (const float*)d_in[9];
    const float* bfc = (const float*)d_in[10];
    float* out = (float*)d_out;

    static bool attr_set = false;
    if (!attr_set) {
        cudaFuncSetAttribute(lstm_persistent_kernel,
                             cudaFuncAttributeMaxDynamicSharedMemorySize, SM_TOTAL);
        attr_set = true;
    }

    lstm_persistent_kernel<<<NCTAS, NTHREADS, SM_TOTAL>>>(
        x, Wf, bf, Wo, bo, Wi, bi, Wg, bg, Wfc, bfc, out);
}

// round 12
// speedup vs baseline: 1.2385x; 1.2354x over previous
#include <cuda_runtime.h>

// x[512,1024,64], W*[128,192], b*[128], Wfc[10,128], bfc[10], out[512,10] fp32.
#define B_TOT    512
#define T_LEN    1024
#define I_DIM    64
#define H_DIM    128
#define C_DIM    10
#define KDIM     192            // I + H
#define BPC      4              // batch rows per CTA
#define NTHREADS 256
#define NCTAS    (B_TOT / BPC)  // 128

#define KREG     96             // k in [0,96): weights in registers
#define KSM      96             // k in [96,192): weights fp32 in SMEM
#define WSTRIDE  100            // floats per row in SMEM (400B: 25 mod 8 = 1 -> conflict-free)

// SMEM layout (floats):
//  WsmA [256][WSTRIDE]  : row0 weights (f or o), k in [96,192)
//  WsmB [256][WSTRIDE]  : row1 weights (i or g), k in [96,192)
//  acts [BPC][KDIM]     : [x_t | h_t] per batch
#define WSMA_OFF   0
#define WSMB_OFF   (256 * WSTRIDE)
#define ACTS_OFF   (2 * 256 * WSTRIDE)
#define SM_FLOATS  (ACTS_OFF + BPC * KDIM)
#define SM_TOTAL   (SM_FLOATS * 4)          // 207872 bytes

// Packed dual-fp32 FMA (Blackwell f32x2): d = a*b + c elementwise on pairs.
__device__ __forceinline__ float2 ffma2(float2 a, float2 b, float2 c) {
    float2 d;
    asm("{\n\t"
        ".reg .b64 ra, rb, rc, rd;\n\t"
        "mov.b64 ra, {%2, %3};\n\t"
        "mov.b64 rb, {%4, %5};\n\t"
        "mov.b64 rc, {%6, %7};\n\t"
        "fma.rn.f32x2 rd, ra, rb, rc;\n\t"
        "mov.b64 {%0, %1}, rd;\n\t"
        "}"
        : "=f"(d.x), "=f"(d.y)
        : "f"(a.x), "f"(a.y), "f"(b.x), "f"(b.y), "f"(c.x), "f"(c.y));
    return d;
}

__global__ void __launch_bounds__(NTHREADS, 1)
lstm_persistent_kernel(const float* __restrict__ x,
                       const float* __restrict__ Wf, const float* __restrict__ bf,
                       const float* __restrict__ Wo, const float* __restrict__ bo,
                       const float* __restrict__ Wi, const float* __restrict__ bi,
                       const float* __restrict__ Wg, const float* __restrict__ bg,
                       const float* __restrict__ Wfc, const float* __restrict__ bfc,
                       float* __restrict__ out)
{
    extern __shared__ float smem[];
    float* WsmA = smem + WSMA_OFF;
    float* WsmB = smem + WSMB_OFF;
    float* acts = smem + ACTS_OFF;   // [BPC][KDIM]

    const int tid  = threadIdx.x;
    const int b0   = blockIdx.x * BPC;
    const int col  = tid >> 1;       // h-column 0..127
    const int role = tid & 1;        // 0: (f,i), 1: (o,g)

    // Gate row sources for this thread (local row index = col in each gate matrix).
    const float* src0 = role ? Wo : Wf;   // row0
    const float* src1 = role ? Wg : Wi;   // row1
    const float  bias0 = role ? bo[col] : bf[col];
    const float  bias1 = role ? bg[col] : bi[col];

    // ---- One-time: load k<96 weights into registers (fp32, no conversion ever) ----
    float2 wr0[KREG / 2], wr1[KREG / 2];
    {
        const float4* s0 = reinterpret_cast<const float4*>(src0 + (size_t)col * KDIM);
        const float4* s1 = reinterpret_cast<const float4*>(src1 + (size_t)col * KDIM);
#pragma unroll
        for (int q = 0; q < KREG / 4; ++q) {
            float4 v0 = __ldg(s0 + q);
            float4 v1 = __ldg(s1 + q);
            wr0[2 * q + 0] = make_float2(v0.x, v0.y);
            wr0[2 * q + 1] = make_float2(v0.z, v0.w);
            wr1[2 * q + 0] = make_float2(v1.x, v1.y);
            wr1[2 * q + 1] = make_float2(v1.z, v1.w);
        }
    }

    // ---- One-time: stage k in [96,192) weights fp32 into SMEM (per-thread blocks) ----
    {
        float4*       dA = reinterpret_cast<float4*>(WsmA + tid * WSTRIDE);
        float4*       dB = reinterpret_cast<float4*>(WsmB + tid * WSTRIDE);
        const float4* sA = reinterpret_cast<const float4*>(src0 + (size_t)col * KDIM + KREG);
        const float4* sB = reinterpret_cast<const float4*>(src1 + (size_t)col * KDIM + KREG);
#pragma unroll
        for (int q = 0; q < KSM / 4; ++q) {
            dA[q] = __ldg(sA + q);
            dB[q] = __ldg(sB + q);
        }
    }

    // ---- Init activations: x(t=0), h = 0 ----
    for (int idx = tid; idx < BPC * H_DIM; idx += NTHREADS) {
        int b = idx >> 7, j = idx & 127;
        acts[b * KDIM + I_DIM + j] = 0.0f;
    }
    for (int idx = tid; idx < BPC * I_DIM; idx += NTHREADS) {
        int b = idx >> 6, i = idx & 63;
        acts[b * KDIM + i] = x[((size_t)(b0 + b) * T_LEN + 0) * I_DIM + i];
    }

    float c_state[BPC];
#pragma unroll
    for (int b = 0; b < BPC; ++b) c_state[b] = 0.0f;

    // x prefetch slot: each thread owns one element (batch bx, feature ix).
    const int bx = tid >> 6;
    const int ix = tid & 63;
    const float* xsrc = x + (size_t)(b0 + bx) * T_LEN * I_DIM + ix;

    // activation helper constants per role (branchless sigmoid/tanh):
    //   role0: sigma(z) = 1/(1+e^-z)            (m1=1, m2=1, m3=0)
    //   role1 second gate: tanh(z) = 2/(1+e^-2z) - 1 (m1=2, m2=2, m3=1)
    const float m1 = role ? 2.0f : 1.0f;
    const float m2 = role ? 2.0f : 1.0f;
    const float m3 = role ? 1.0f : 0.0f;

    const float4* wa = reinterpret_cast<const float4*>(WsmA + tid * WSTRIDE);
    const float4* wb = reinterpret_cast<const float4*>(WsmB + tid * WSTRIDE);

    __syncthreads();

    for (int t = 0; t < T_LEN; ++t) {
        float xnext = 0.0f;
        if (t + 1 < T_LEN) xnext = __ldg(xsrc + (size_t)(t + 1) * I_DIM);

        float2 acc0[BPC], acc1[BPC];
#pragma unroll
        for (int b = 0; b < BPC; ++b) {
            acc0[b] = make_float2(0.0f, 0.0f);
            acc1[b] = make_float2(0.0f, 0.0f);
        }

        // ---- Part 1: k in [0,96), weights in registers (no LDS, no converts) ----
#pragma unroll
        for (int kc = 0; kc < KREG / 8; ++kc) {
#pragma unroll
            for (int b = 0; b < BPC; ++b) {
                const float4* ap = reinterpret_cast<const float4*>(acts + b * KDIM + kc * 8);
                float4 A0 = ap[0];
                float4 A1 = ap[1];
                float2 p0 = make_float2(A0.x, A0.y);
                float2 p1 = make_float2(A0.z, A0.w);
                float2 p2 = make_float2(A1.x, A1.y);
                float2 p3 = make_float2(A1.z, A1.w);
                acc0[b] = ffma2(wr0[kc * 4 + 0], p0, acc0[b]);
                acc0[b] = ffma2(wr0[kc * 4 + 1], p1, acc0[b]);
                acc0[b] = ffma2(wr0[kc * 4 + 2], p2, acc0[b]);
                acc0[b] = ffma2(wr0[kc * 4 + 3], p3, acc0[b]);
                acc1[b] = ffma2(wr1[kc * 4 + 0], p0, acc1[b]);
                acc1[b] = ffma2(wr1[kc * 4 + 1], p1, acc1[b]);
                acc1[b] = ffma2(wr1[kc * 4 + 2], p2, acc1[b]);
                acc1[b] = ffma2(wr1[kc * 4 + 3], p3, acc1[b]);
            }
        }

        // ---- Part 2: k in [96,192), weights fp32 from SMEM ----
#pragma unroll 2
        for (int kc = 0; kc < KSM / 8; ++kc) {
            float4 u0a = wa[kc * 2 + 0];
            float4 u0b = wa[kc * 2 + 1];
            float4 u1a = wb[kc * 2 + 0];
            float4 u1b = wb[kc * 2 + 1];
            float2 w00 = make_float2(u0a.x, u0a.y);
            float2 w01 = make_float2(u0a.z, u0a.w);
            float2 w02 = make_float2(u0b.x, u0b.y);
            float2 w03 = make_float2(u0b.z, u0b.w);
            float2 w10 = make_float2(u1a.x, u1a.y);
            float2 w11 = make_float2(u1a.z, u1a.w);
            float2 w12 = make_float2(u1b.x, u1b.y);
            float2 w13 = make_float2(u1b.z, u1b.w);
#pragma unroll
            for (int b = 0; b < BPC; ++b) {
                const float4* ap = reinterpret_cast<const float4*>(acts + b * KDIM + KREG + kc * 8);
                float4 A0 = ap[0];
                float4 A1 = ap[1];
                float2 p0 = make_float2(A0.x, A0.y);
                float2 p1 = make_float2(A0.z, A0.w);
                float2 p2 = make_float2(A1.x, A1.y);
                float2 p3 = make_float2(A1.z, A1.w);
                acc0[b] = ffma2(w00, p0, acc0[b]);
                acc0[b] = ffma2(w01, p1, acc0[b]);
                acc0[b] = ffma2(w02, p2, acc0[b]);
                acc0[b] = ffma2(w03, p3, acc0[b]);
                acc1[b] = ffma2(w10, p0, acc1[b]);
                acc1[b] = ffma2(w11, p1, acc1[b]);
                acc1[b] = ffma2(w12, p2, acc1[b]);
                acc1[b] = ffma2(w13, p3, acc1[b]);
            }
        }

        __syncthreads();   // all acts reads done before anyone writes acts

        // ---- Elementwise + intra-warp (f,i)<->(o,g) exchange via shfl ----
#pragma unroll
        for (int b = 0; b < BPC; ++b) {
            float p0 = acc0[b].x + acc0[b].y + bias0;      // f or o preact
            float p1 = acc1[b].x + acc1[b].y + bias1;      // i or g preact
            float a0 = 1.0f / (1.0f + __expf(-p0));        // sigma: fs or os
            float a1 = m2 / (1.0f + __expf(-p1 * m1)) - m3; // is (sigma) or gt (tanh)
            float o0 = __shfl_xor_sync(0xFFFFFFFFu, a0, 1);
            float o1 = __shfl_xor_sync(0xFFFFFFFFu, a1, 1);
            float fs = role ? o0 : a0;
            float is = role ? o1 : a1;
            float os = role ? a0 : o0;
            float gt = role ? a1 : o1;
            float c  = c_state[b] * fs + gt * is;
            c_state[b] = c;
            float h  = c * os;
            // role0 writes batches 0,1; role1 writes batches 2,3 (identical values)
            if ((b < 2) == (role == 0))
                acts[b * KDIM + I_DIM + col] = h;
        }
        if (t + 1 < T_LEN) acts[bx * KDIM + ix] = xnext;   // stage x_{t+1}

        __syncthreads();   // h and x visible for next step
    }

    // ---- Final FC: out[b, c] = h[b,:] . Wfc[c,:] + bfc[c] ----
    for (int idx = tid; idx < BPC * C_DIM; idx += NTHREADS) {
        int b  = idx / C_DIM;
        int cc = idx - b * C_DIM;
        float s = bfc[cc];
        const float* hrow = acts + b * KDIM + I_DIM;
        const float* wrow = Wfc + cc * H_DIM;
#pragma unroll 8
        for (int k = 0; k < H_DIM; ++k)
            s += hrow[k] * wrow[k];
        out[(b0 + b) * C_DIM + cc] = s;
    }
}

extern "C" void kernel_launch(void* const* d_in, const int* in_sizes, int n_in,
                              void* d_out, int out_size)
{
    const float* x   = (const float*)d_in[0];
    const float* Wf  = (const float*)d_in[1];
    const float* bf  = (const float*)d_in[2];
    const float* Wo  = (const float*)d_in[3];
    const float* bo  = (const float*)d_in[4];
    const float* Wi  = (const float*)d_in[5];
    const float* bi  = (const float*)d_in[6];
    const float* Wg  = (const float*)d_in[7];
    const float* bg  = (const float*)d_in[8];
    const float* Wfc = (const float*)d_in[9];
    const float* bfc = (const float*)d_in[10];
    float* out = (float*)d_out;

    static bool attr_set = false;
    if (!attr_set) {
        cudaFuncSetAttribute(lstm_persistent_kernel,
                             cudaFuncAttributeMaxDynamicSharedMemorySize, SM_TOTAL);
        attr_set = true;
    }

    lstm_persistent_kernel<<<NCTAS, NTHREADS, SM_TOTAL>>>(
        x, Wf, bf, Wo, bo, Wi, bi, Wg, bg, Wfc, bfc, out);
}